// round 15
// baseline (speedup 1.0000x reference)
#include <cuda_runtime.h>
#include <cuda_bf16.h>
#include <math.h>

#define BB 8
#define TT 1024
#define EE 1024
#define HH 16
#define DD 64

// Scratch (allocation-free rule: __device__ globals).
__device__ __nv_bfloat16 g_q2[BB*HH*TT*DD];   // Q/256 as bf16, packed per head
__device__ __nv_bfloat16 g_nw[BB*HH*TT*DD];   // RNN key history as bf16
__device__ __nv_bfloat16 g_v2t[BB*HH*DD*TT];  // V transposed [bh][d][t] bf16
__device__ float g_vsum[BB*HH*DD];            // Sum_t V[bh][t][d] (fp32 exact)
__device__ float g_wvo[HH*DD*DD];             // W_v @ W_o per head (bias-rounded)
__device__ float g_hstate[BB*HH*DD];          // RNN state handoff between halves
__device__ float g_opart[34*1024*256];        // attn partial o (32) + l0,l1 per thread

__device__ __forceinline__ unsigned cvt_tf32(float f) {
    unsigned r; asm("cvt.rna.tf32.f32 %0, %1;" : "=r"(r) : "f"(f)); return r;
}
__device__ __forceinline__ float bias_tf32(float f) {
    return __uint_as_float(__float_as_uint(f) + 0x1000u);
}
__device__ __forceinline__ unsigned pack_bf16(float lo, float hi) {
    unsigned r; asm("cvt.rn.bf16x2.f32 %0, %1, %2;" : "=r"(r) : "f"(hi), "f"(lo)); return r;
}
__device__ __forceinline__ void mma8(float* d, const unsigned* a, unsigned b0, unsigned b1) {
    asm volatile("mma.sync.aligned.m16n8k8.row.col.f32.tf32.tf32.f32 "
                 "{%0,%1,%2,%3}, {%4,%5,%6,%7}, {%8,%9}, {%0,%1,%2,%3};"
                 : "+f"(d[0]), "+f"(d[1]), "+f"(d[2]), "+f"(d[3])
                 : "r"(a[0]), "r"(a[1]), "r"(a[2]), "r"(a[3]), "r"(b0), "r"(b1));
}
__device__ __forceinline__ void mma16(float* d, const unsigned* a, unsigned b0, unsigned b1) {
    asm volatile("mma.sync.aligned.m16n8k16.row.col.f32.bf16.bf16.f32 "
                 "{%0,%1,%2,%3}, {%4,%5,%6,%7}, {%8,%9}, {%0,%1,%2,%3};"
                 : "+f"(d[0]), "+f"(d[1]), "+f"(d[2]), "+f"(d[3])
                 : "r"(a[0]), "r"(a[1]), "r"(a[2]), "r"(a[3]), "r"(b0), "r"(b1));
}
__device__ __forceinline__ void ldsm4(unsigned& r0, unsigned& r1, unsigned& r2,
                                      unsigned& r3, unsigned addr) {
    asm volatile("ldmatrix.sync.aligned.m8n8.x4.shared.b16 {%0,%1,%2,%3}, [%4];"
                 : "=r"(r0), "=r"(r1), "=r"(r2), "=r"(r3) : "r"(addr));
}
__device__ __forceinline__ float fast_tanh(float x) {
    float r; asm("tanh.approx.f32 %0, %1;" : "=f"(r) : "f"(x)); return r;
}
__device__ __forceinline__ void cpa16(unsigned dst, const void* src) {
    asm volatile("cp.async.cg.shared.global [%0], [%1], 16;" :: "r"(dst), "l"(src));
}
// expm1(x) for |x| <= ~0.03: quadratic, abs err < 5e-6 (below bf16 pack noise)
__device__ __forceinline__ float expm1_tiny(float x) {
    return x * fmaf(x, 0.5f, 1.0f);
}

// ---------------------------------------------------------------------------
// Prep A: W_vo[h] = W_v[h] @ W_o[h] (fp32 accumulate, bias-rounded store).
// ---------------------------------------------------------------------------
__global__ __launch_bounds__(256) void prep_kernel(const float* __restrict__ Wv,
                                                   const float* __restrict__ Wo) {
    __shared__ float Is[64*64];
    __shared__ float Ws[64*64];
    int h = blockIdx.x, tid = threadIdx.x;

    const float4* a4 = (const float4*)(Wv + h*4096);
    const float4* b4 = (const float4*)(Wo + h*4096);
    for (int i = tid; i < 1024; i += 256) { ((float4*)Is)[i] = a4[i]; ((float4*)Ws)[i] = b4[i]; }
    __syncthreads();

    int tx = tid & 15, ty = tid >> 4;
    int row0 = ty*4, col0 = tx*4;
    float acc[4][4];
    #pragma unroll
    for (int i=0;i<4;i++)
        #pragma unroll
        for (int j=0;j<4;j++) acc[i][j]=0.f;
    #pragma unroll 4
    for (int k4 = 0; k4 < 16; k4++) {
        float a[4][4];
        #pragma unroll
        for (int i=0;i<4;i++) *(float4*)a[i] = *(const float4*)&Is[(row0+i)*64 + k4*4];
        #pragma unroll
        for (int kk=0;kk<4;kk++) {
            float bv[4];
            *(float4*)bv = *(const float4*)&Ws[(k4*4+kk)*64 + col0];
            #pragma unroll
            for (int i=0;i<4;i++)
                #pragma unroll
                for (int j=0;j<4;j++) acc[i][j] += a[i][kk]*bv[j];
        }
    }
    #pragma unroll
    for (int i=0;i<4;i++) {
        float4 v = make_float4(bias_tf32(acc[i][0]), bias_tf32(acc[i][1]),
                               bias_tf32(acc[i][2]), bias_tf32(acc[i][3]));
        *(float4*)(g_wvo + h*4096 + (row0+i)*64 + col0) = v;
    }
}

// ---------------------------------------------------------------------------
// Prep B: Vsum[bh][d] = Sum_t tgt[b,t,h*64+d].
// 256 threads: thread (q,d) sums t in [256q, 256q+256); fixed-order combine
// (deterministic, 4x the memory-level parallelism of the 64-thread version).
// ---------------------------------------------------------------------------
__global__ __launch_bounds__(256) void vsum_kernel(const float* __restrict__ tgt) {
    __shared__ float ps[4][64];
    int bh = blockIdx.x;
    int b = bh >> 4, h = bh & 15;
    int d = threadIdx.x & 63;
    int q = threadIdx.x >> 6;
    const float* p = tgt + ((size_t)b*TT + q*256)*EE + h*DD + d;
    float s = 0.f;
    #pragma unroll 8
    for (int t = 0; t < 256; t++) s += p[(size_t)t*EE];
    ps[q][d] = s;
    __syncthreads();
    if (threadIdx.x < 64) {
        int dd = threadIdx.x;
        g_vsum[bh*DD + dd] = ((ps[0][dd] + ps[1][dd]) + (ps[2][dd] + ps[3][dd]));
    }
}

// ---------------------------------------------------------------------------
// Prep C: V transpose to bf16:  g_v2t[bh][d][t] = bf16(tgt[b,t,h*64+d]).
// ---------------------------------------------------------------------------
__global__ __launch_bounds__(256) void vtrans_kernel(const float* __restrict__ tgt) {
    __shared__ float ts[64*68];
    int tt = blockIdx.x, h = blockIdx.y, b = blockIdx.z;
    int bh = b*HH + h;
    int tid = threadIdx.x;

    for (int i = tid; i < 1024; i += 256) {
        int r = i >> 4, c4 = i & 15;
        *(float4*)&ts[r*68 + c4*4] =
            *(const float4*)(tgt + ((size_t)b*TT + tt*64 + r)*EE + h*DD + c4*4);
    }
    __syncthreads();

    for (int j = tid; j < 512; j += 256) {
        int d = j >> 3, ch = j & 7;
        uint4 u;
        u.x = pack_bf16(ts[(ch*8+0)*68 + d], ts[(ch*8+1)*68 + d]);
        u.y = pack_bf16(ts[(ch*8+2)*68 + d], ts[(ch*8+3)*68 + d]);
        u.z = pack_bf16(ts[(ch*8+4)*68 + d], ts[(ch*8+5)*68 + d]);
        u.w = pack_bf16(ts[(ch*8+6)*68 + d], ts[(ch*8+7)*68 + d]);
        ((uint4*)g_v2t)[(size_t)(bh*64 + d)*128 + tt*8 + ch] = u;
    }
}

// ---------------------------------------------------------------------------
// Q projection: q2 = (src @ W_q[h]) / 256, stored bf16 packed per head.
// ---------------------------------------------------------------------------
__global__ __launch_bounds__(256) void proj_kernel(const float* __restrict__ src,
                                                   const float* __restrict__ Wq) {
    __shared__ float Is[64*64];
    __shared__ float Ws[64*64];
    int tt = blockIdx.x, h = blockIdx.y, b = blockIdx.z;
    const float* W = Wq + h * 4096;
    __nv_bfloat16* outp = g_q2 + ((size_t)(b*HH + h)*TT + tt*64)*DD;
    int tid = threadIdx.x;

    for (int i = tid; i < 1024; i += 256) ((float4*)Ws)[i] = ((const float4*)W)[i];
    for (int i = tid; i < 1024; i += 256) {
        int r = i >> 4, c4 = i & 15;
        ((float4*)Is)[i] = *(const float4*)(src + ((size_t)b*TT + tt*64 + r)*EE + h*DD + c4*4);
    }
    __syncthreads();

    int tx = tid & 15, ty = tid >> 4;
    int row0 = ty*4, col0 = tx*4;
    float acc[4][4];
    #pragma unroll
    for (int i=0;i<4;i++)
        #pragma unroll
        for (int j=0;j<4;j++) acc[i][j]=0.f;

    #pragma unroll 4
    for (int k4 = 0; k4 < 16; k4++) {
        float a[4][4];
        #pragma unroll
        for (int i=0;i<4;i++) *(float4*)a[i] = *(const float4*)&Is[(row0+i)*64 + k4*4];
        #pragma unroll
        for (int kk=0;kk<4;kk++) {
            float bv[4];
            *(float4*)bv = *(const float4*)&Ws[(k4*4+kk)*64 + col0];
            #pragma unroll
            for (int i=0;i<4;i++)
                #pragma unroll
                for (int j=0;j<4;j++) acc[i][j] += a[i][kk]*bv[j];
        }
    }
    const float s = 1.0f/256.0f;
    #pragma unroll
    for (int i=0;i<4;i++) {
        uint2 u;
        u.x = pack_bf16(acc[i][0]*s, acc[i][1]*s);
        u.y = pack_bf16(acc[i][2]*s, acc[i][3]*s);
        *(uint2*)(outp + (row0+i)*64 + col0) = u;
    }
}

// ---------------------------------------------------------------------------
// RNN recurrence over t in [t0, t1). One block per (b,h), 128 threads,
// 2 threads per row. t0==0 runs the k0 init step; otherwise state is loaded
// from g_hstate. State is saved to g_hstate at the end (exact fp32).
// ---------------------------------------------------------------------------
__global__ __launch_bounds__(128) void rnn_kernel(const float* __restrict__ tgt,
                                                  const float* __restrict__ Wih,
                                                  const float* __restrict__ Whh,
                                                  const float* __restrict__ bih,
                                                  const float* __restrict__ bhh,
                                                  int t0, int t1) {
    __shared__ __align__(16) float hs[2][64];
    __shared__ __align__(16) float k0s[64];
    int bh = blockIdx.x;
    int b = bh >> 4, h = bh & 15;
    int tid = threadIdx.x;
    int r = tid >> 1, half = tid & 1;

    float c = bih[h*DD + r] + bhh[h*DD + r];
    float Wr[32];
    __nv_bfloat16* nwp = g_nw + (size_t)bh*TT*DD;
    int cur = 0;

    if (t0 == 0) {
        if (tid < 64) k0s[tid] = tgt[(size_t)b*TT*EE + h*DD + tid];
        const float* wi = Wih + (size_t)(h*DD + r)*DD + half*32;
        #pragma unroll
        for (int d4 = 0; d4 < 8; d4++) *(float4*)&Wr[d4*4] = *(const float4*)&wi[d4*4];
        __syncthreads();

        {
            const float* hc = k0s + half*32;
            float a0=0.f,a1=0.f,a2=0.f,a3=0.f;
            #pragma unroll
            for (int d4 = 0; d4 < 8; d4++) {
                float hv[4]; *(float4*)hv = *(const float4*)&hc[d4*4];
                a0 += Wr[d4*4+0]*hv[0]; a1 += Wr[d4*4+1]*hv[1];
                a2 += Wr[d4*4+2]*hv[2]; a3 += Wr[d4*4+3]*hv[3];
            }
            float p = (a0+a1)+(a2+a3);
            p += __shfl_xor_sync(0xffffffffu, p, 1);
            float hv1 = fast_tanh(p + c);
            if (half == 0) hs[0][r] = hv1;
            else           nwp[r] = __float2bfloat16(hv1);
        }
        const float* wh = Whh + (size_t)(h*DD + r)*DD + half*32;
        #pragma unroll
        for (int d4 = 0; d4 < 8; d4++) {
            float t4[4]; *(float4*)t4 = *(const float4*)&wh[d4*4];
            Wr[d4*4+0] += t4[0]; Wr[d4*4+1] += t4[1];
            Wr[d4*4+2] += t4[2]; Wr[d4*4+3] += t4[3];
        }
        __syncthreads();
        t0 = 1;
    } else {
        const float* wi = Wih + (size_t)(h*DD + r)*DD + half*32;
        const float* wh = Whh + (size_t)(h*DD + r)*DD + half*32;
        #pragma unroll
        for (int d4 = 0; d4 < 8; d4++) {
            float a4[4]; *(float4*)a4 = *(const float4*)&wi[d4*4];
            float t4[4]; *(float4*)t4 = *(const float4*)&wh[d4*4];
            Wr[d4*4+0] = a4[0]+t4[0]; Wr[d4*4+1] = a4[1]+t4[1];
            Wr[d4*4+2] = a4[2]+t4[2]; Wr[d4*4+3] = a4[3]+t4[3];
        }
        if (tid < 64) hs[0][tid] = g_hstate[bh*DD + tid];
        __syncthreads();
    }

    for (int t = t0; t < t1; t++) {
        const float* hc = hs[cur] + half*32;
        float a0=0.f,a1=0.f,a2=0.f,a3=0.f;
        #pragma unroll
        for (int d4 = 0; d4 < 8; d4++) {
            float hv[4]; *(float4*)hv = *(const float4*)&hc[d4*4];
            a0 += Wr[d4*4+0]*hv[0]; a1 += Wr[d4*4+1]*hv[1];
            a2 += Wr[d4*4+2]*hv[2]; a3 += Wr[d4*4+3]*hv[3];
        }
        float p = (a0+a1)+(a2+a3);
        p += __shfl_xor_sync(0xffffffffu, p, 1);
        float hn = fast_tanh(p + c);
        if (half == 0) hs[cur^1][r] = hn;
        else           nwp[(size_t)t*DD + r] = __float2bfloat16(hn);
        cur ^= 1;
        __syncthreads();
    }

    if (tid < 64) g_hstate[bh*DD + tid] = hs[cur][tid];
}

// ---------------------------------------------------------------------------
// Flash attention over key tiles [kt0, kt1), mean-subtracted, resumable:
//   O += E @ V,  l += sum(E);  E = expm1(scores)
// first=0 loads partials from g_opart; last=0 stores them; last=1 runs the
// fused (Vsum + O)/(1024+l) @ W_vo epilogue. Partials are exact fp32, so the
// split is bit-identical to the single-pass version.
// ---------------------------------------------------------------------------
#define STG3_W 4608

__global__ __launch_bounds__(256, 2) void attn_kernel(float* __restrict__ out,
                                                      int kt0, int kt1,
                                                      int first, int last) {
    extern __shared__ float sm[];   // 13824 words
    unsigned* smw = (unsigned*)sm;
    int qt = blockIdx.x, h = blockIdx.y, b = blockIdx.z;
    int bh = b*HH + h;
    int tid = threadIdx.x;
    int w = tid >> 5, lane = tid & 31;
    int gq = lane >> 2;
    int tg = lane & 3;
    int r0 = w * 16;
    unsigned sb = (unsigned)__cvta_generic_to_shared(sm);
    unsigned lmo = (unsigned)(((((lane>>4)*8 + (lane&7))*36) + ((lane>>3)&1)*4) * 4);
    int gid = ((b*HH + h)*8 + qt)*256 + tid;   // partials index

    // ---- stage Q tile [128][64] bf16 -> smem word pitch 36; extract frags ----
    {
        const uint4* qsrc = (const uint4*)(g_q2 + ((size_t)bh*TT + qt*128)*DD);
        #pragma unroll
        for (int j = 0; j < 4; j++) {
            int idx = tid + j*256;
            int r = idx >> 3, c = idx & 7;
            cpa16(sb + ((unsigned)(r*36 + c*4))*4u, qsrc + idx);
        }
        asm volatile("cp.async.commit_group;");
        asm volatile("cp.async.wait_group 0;");
    }
    __syncthreads();
    unsigned qa[4][4];
    #pragma unroll
    for (int k = 0; k < 4; k++) {
        qa[k][0] = smw[(r0+gq  )*36 + k*8 + tg  ];
        qa[k][1] = smw[(r0+gq+8)*36 + k*8 + tg  ];
        qa[k][2] = smw[(r0+gq  )*36 + k*8 + tg+4];
        qa[k][3] = smw[(r0+gq+8)*36 + k*8 + tg+4];
    }
    __syncthreads();   // frags in regs before staging overwrites

    const uint4* kg = (const uint4*)(g_nw + (size_t)bh*TT*DD);
    const uint4* vt = (const uint4*)g_v2t + (size_t)(bh*64)*128;

    // ---- prologue: stage tiles kt0, kt0+1 ----
    #pragma unroll
    for (int pt = 0; pt < 2; pt++) {
        int ktp = kt0 + pt;
        unsigned bb = (unsigned)((ktp % 3) * STG3_W) * 4u;
        const uint4* kp = kg + (size_t)ktp*512;
        const uint4* vp = vt + ktp*8;
        #pragma unroll
        for (int j = 0; j < 2; j++) {
            int idx = tid + j*256;
            int r = idx >> 3, c = idx & 7;
            cpa16(sb + bb + ((unsigned)(r*36 + c*4))*4u, kp + idx);
        }
        #pragma unroll
        for (int j = 0; j < 2; j++) {
            int idx = tid + j*256;
            int d = idx >> 3, c = idx & 7;
            cpa16(sb + bb + ((unsigned)(2304 + d*36 + c*4))*4u, vp + (size_t)d*128 + c);
        }
        asm volatile("cp.async.commit_group;");
    }

    float l0, l1;
    float o[8][4];
    if (first) {
        l0 = 0.f; l1 = 0.f;
        #pragma unroll
        for (int n=0;n<8;n++) { o[n][0]=0.f;o[n][1]=0.f;o[n][2]=0.f;o[n][3]=0.f; }
    } else {
        #pragma unroll
        for (int n=0;n<8;n++)
            #pragma unroll
            for (int j=0;j<4;j++) o[n][j] = g_opart[(size_t)(n*4+j)*262144 + gid];
        l0 = g_opart[(size_t)32*262144 + gid];
        l1 = g_opart[(size_t)33*262144 + gid];
    }

    for (int kt = kt0; kt < kt1; kt++) {
        if (kt < kt1-1) asm volatile("cp.async.wait_group 1;");
        else            asm volatile("cp.async.wait_group 0;");
        __syncthreads();   // tile kt ready; all warps done reading tile kt-1

        if (kt < kt1-2) {
            int ktn = kt + 2;
            unsigned bb = (unsigned)((ktn % 3) * STG3_W) * 4u;
            const uint4* kp = kg + (size_t)ktn*512;
            const uint4* vp = vt + ktn*8;
            #pragma unroll
            for (int j = 0; j < 2; j++) {
                int idx = tid + j*256;
                int r = idx >> 3, c = idx & 7;
                cpa16(sb + bb + ((unsigned)(r*36 + c*4))*4u, kp + idx);
            }
            #pragma unroll
            for (int j = 0; j < 2; j++) {
                int idx = tid + j*256;
                int d = idx >> 3, c = idx & 7;
                cpa16(sb + bb + ((unsigned)(2304 + d*36 + c*4))*4u, vp + (size_t)d*128 + c);
            }
            asm volatile("cp.async.commit_group;");
        }

        unsigned kaddr = sb + (unsigned)((kt % 3) * STG3_W) * 4u + lmo;
        unsigned vaddr = kaddr + 2304u*4u;

        // ---- S = Q @ K^T ----
        float s[8][4];
        #pragma unroll
        for (int n=0;n<8;n++) { s[n][0]=0.f;s[n][1]=0.f;s[n][2]=0.f;s[n][3]=0.f; }
        #pragma unroll
        for (int np = 0; np < 4; np++) {
            #pragma unroll
            for (int k = 0; k < 4; k++) {
                unsigned b0, b1, b2, b3;
                ldsm4(b0, b1, b2, b3, kaddr + (unsigned)np*2304u + (unsigned)k*32u);
                mma16(s[2*np  ], qa[k], b0, b1);
                mma16(s[2*np+1], qa[k], b2, b3);
            }
        }

        // ---- E = expm1(s); l += sum(E) ----
        float ls0 = 0.f, ls1 = 0.f;
        #pragma unroll
        for (int n = 0; n < 8; n++) {
            s[n][0] = expm1_tiny(s[n][0]); s[n][1] = expm1_tiny(s[n][1]);
            s[n][2] = expm1_tiny(s[n][2]); s[n][3] = expm1_tiny(s[n][3]);
            ls0 += s[n][0] + s[n][1];
            ls1 += s[n][2] + s[n][3];
        }
        ls0 += __shfl_xor_sync(0xffffffffu, ls0, 1);
        ls0 += __shfl_xor_sync(0xffffffffu, ls0, 2);
        ls1 += __shfl_xor_sync(0xffffffffu, ls1, 1);
        ls1 += __shfl_xor_sync(0xffffffffu, ls1, 2);
        l0 += ls0;
        l1 += ls1;

        // ---- O += E @ V ----
        unsigned ap[4][4];
        #pragma unroll
        for (int m = 0; m < 4; m++) {
            ap[m][0] = pack_bf16(s[2*m  ][0], s[2*m  ][1]);
            ap[m][1] = pack_bf16(s[2*m  ][2], s[2*m  ][3]);
            ap[m][2] = pack_bf16(s[2*m+1][0], s[2*m+1][1]);
            ap[m][3] = pack_bf16(s[2*m+1][2], s[2*m+1][3]);
        }
        #pragma unroll
        for (int np = 0; np < 4; np++) {
            #pragma unroll
            for (int m = 0; m < 4; m++) {
                unsigned b0, b1, b2, b3;
                ldsm4(b0, b1, b2, b3, vaddr + (unsigned)np*2304u + (unsigned)m*32u);
                mma16(o[2*np  ], ap[m], b0, b1);
                mma16(o[2*np+1], ap[m], b2, b3);
            }
        }
    }

    if (!last) {
        // ---- store partials (exact fp32) and exit ----
        #pragma unroll
        for (int n=0;n<8;n++)
            #pragma unroll
            for (int j=0;j<4;j++) g_opart[(size_t)(n*4+j)*262144 + gid] = o[n][j];
        g_opart[(size_t)32*262144 + gid] = l0;
        g_opart[(size_t)33*262144 + gid] = l1;
        return;
    }
    __syncthreads();   // all tile reads done before epilogue reuses smem

    // ---- fused epilogue: out_rows = ((Vsum + O)/(1024 + l)) @ W_vo[h] ----
    float inv0 = 1.0f/(1024.f + l0), inv1 = 1.0f/(1024.f + l1);
    float2 vs[8];
    #pragma unroll
    for (int n = 0; n < 8; n++)
        vs[n] = *(const float2*)&g_vsum[bh*64 + n*8 + 2*tg];

    float* Os = sm;              // pitch 72, words [0, 9216)
    float* WvT = sm + 9216;      // words [9216, 13824)
    #pragma unroll
    for (int n = 0; n < 8; n++) {
        Os[(r0+gq  )*72 + n*8 + 2*tg  ] = (o[n][0]+vs[n].x)*inv0;
        Os[(r0+gq  )*72 + n*8 + 2*tg+1] = (o[n][1]+vs[n].y)*inv0;
        Os[(r0+gq+8)*72 + n*8 + 2*tg  ] = (o[n][2]+vs[n].x)*inv1;
        Os[(r0+gq+8)*72 + n*8 + 2*tg+1] = (o[n][3]+vs[n].y)*inv1;
    }
    const float* wv = g_wvo + h*4096;   // already bias-rounded
    for (int i = tid; i < 1024; i += 256) {
        int k = i >> 4, n4 = (i & 15) * 4;
        float4 v = *(const float4*)(wv + k*64 + n4);
        WvT[(n4  )*72 + k] = v.x;
        WvT[(n4+1)*72 + k] = v.y;
        WvT[(n4+2)*72 + k] = v.z;
        WvT[(n4+3)*72 + k] = v.w;
    }
    __syncthreads();

    float r2[8][4];
    #pragma unroll
    for (int n=0;n<8;n++) { r2[n][0]=0.f;r2[n][1]=0.f;r2[n][2]=0.f;r2[n][3]=0.f; }
    #pragma unroll
    for (int k = 0; k < 8; k++) {
        unsigned a[4];
        a[0] = cvt_tf32(Os[(r0+gq  )*72 + k*8 + tg  ]);
        a[1] = cvt_tf32(Os[(r0+gq+8)*72 + k*8 + tg  ]);
        a[2] = cvt_tf32(Os[(r0+gq  )*72 + k*8 + tg+4]);
        a[3] = cvt_tf32(Os[(r0+gq+8)*72 + k*8 + tg+4]);
        #pragma unroll
        for (int n = 0; n < 8; n++) {
            unsigned b0 = __float_as_uint(WvT[(n*8+gq)*72 + k*8 + tg  ]);
            unsigned b1 = __float_as_uint(WvT[(n*8+gq)*72 + k*8 + tg+4]);
            mma8(r2[n], a, b0, b1);
        }
    }
    float* op = out + ((size_t)b*TT + qt*128)*EE + h*DD;
    #pragma unroll
    for (int n = 0; n < 8; n++) {
        *(float2*)(op + (size_t)(r0+gq  )*EE + n*8 + 2*tg) = make_float2(r2[n][0], r2[n][1]);
        *(float2*)(op + (size_t)(r0+gq+8)*EE + n*8 + 2*tg) = make_float2(r2[n][2], r2[n][3]);
    }
}

// ---------------------------------------------------------------------------
extern "C" void kernel_launch(void* const* d_in, const int* in_sizes, int n_in,
                              void* d_out, int out_size) {
    const float* src = (const float*)d_in[0];
    const float* tgt = (const float*)d_in[1];
    const float* Wq  = (const float*)d_in[2];
    const float* Wv  = (const float*)d_in[3];
    const float* Wo  = (const float*)d_in[4];
    const float* Wih = (const float*)d_in[5];
    const float* Whh = (const float*)d_in[6];
    const float* bih = (const float*)d_in[7];
    const float* bhh = (const float*)d_in[8];
    float* out = (float*)d_out;

    // One-time infra (host-side only; no device memory).
    static cudaStream_t s_rnn = nullptr, s_aux = nullptr;
    static cudaEvent_t ev_fork = nullptr, ev_r1 = nullptr, ev_r2 = nullptr, ev_aux = nullptr;
    if (s_rnn == nullptr) {
        cudaStreamCreateWithFlags(&s_rnn, cudaStreamNonBlocking);
        cudaStreamCreateWithFlags(&s_aux, cudaStreamNonBlocking);
        cudaEventCreateWithFlags(&ev_fork, cudaEventDisableTiming);
        cudaEventCreateWithFlags(&ev_r1, cudaEventDisableTiming);
        cudaEventCreateWithFlags(&ev_r2, cudaEventDisableTiming);
        cudaEventCreateWithFlags(&ev_aux, cudaEventDisableTiming);
        cudaFuncSetAttribute(attn_kernel, cudaFuncAttributeMaxDynamicSharedMemorySize,
                             3 * STG3_W * (int)sizeof(float));
    }

    cudaEventRecord(ev_fork, 0);

    // stream R: the serial RNN, split in halves.
    cudaStreamWaitEvent(s_rnn, ev_fork, 0);
    rnn_kernel<<<128, 128, 0, s_rnn>>>(tgt, Wih, Whh, bih, bhh, 0, 512);
    cudaEventRecord(ev_r1, s_rnn);
    rnn_kernel<<<128, 128, 0, s_rnn>>>(tgt, Wih, Whh, bih, bhh, 512, 1024);
    cudaEventRecord(ev_r2, s_rnn);

    // stream AUX: inputs needed only by attn chunk 2's epilogue.
    cudaStreamWaitEvent(s_aux, ev_fork, 0);
    prep_kernel<<<16, 256, 0, s_aux>>>(Wv, Wo);
    vsum_kernel<<<128, 256, 0, s_aux>>>(tgt);
    cudaEventRecord(ev_aux, s_aux);

    // stream 0: inputs needed by attn chunk 1 (shortest chain).
    vtrans_kernel<<<dim3(16,16,8), 256>>>(tgt);
    proj_kernel<<<dim3(16,16,8), 256>>>(src, Wq);

    cudaStreamWaitEvent(0, ev_r1, 0);
    attn_kernel<<<dim3(8, 16, 8), 256, 3 * STG3_W * sizeof(float)>>>(out, 0, 8, 1, 0);
    cudaStreamWaitEvent(0, ev_r2, 0);
    cudaStreamWaitEvent(0, ev_aux, 0);
    attn_kernel<<<dim3(8, 16, 8), 256, 3 * STG3_W * sizeof(float)>>>(out, 8, 16, 0, 1);
}

// round 16
// speedup vs baseline: 1.2358x; 1.2358x over previous
#include <cuda_runtime.h>
#include <cuda_bf16.h>
#include <math.h>

#define BB 8
#define TT 1024
#define EE 1024
#define HH 16
#define DD 64

// Scratch (allocation-free rule: __device__ globals).
__device__ __nv_bfloat16 g_q2[BB*HH*TT*DD];   // Q/256 as bf16, packed per head
__device__ __nv_bfloat16 g_nw[BB*HH*TT*DD];   // RNN key history as bf16
__device__ __nv_bfloat16 g_v2t[BB*HH*DD*TT];  // V transposed [bh][d][t] bf16
__device__ float g_vsum[BB*HH*DD];            // Sum_t V[bh][t][d] (fp32 exact)
__device__ float g_wvo[HH*DD*DD];             // W_v @ W_o per head (bias-rounded)

__device__ __forceinline__ unsigned cvt_tf32(float f) {
    unsigned r; asm("cvt.rna.tf32.f32 %0, %1;" : "=r"(r) : "f"(f)); return r;
}
__device__ __forceinline__ float bias_tf32(float f) {
    return __uint_as_float(__float_as_uint(f) + 0x1000u);
}
__device__ __forceinline__ unsigned pack_bf16(float lo, float hi) {
    unsigned r; asm("cvt.rn.bf16x2.f32 %0, %1, %2;" : "=r"(r) : "f"(hi), "f"(lo)); return r;
}
__device__ __forceinline__ void mma8(float* d, const unsigned* a, unsigned b0, unsigned b1) {
    asm volatile("mma.sync.aligned.m16n8k8.row.col.f32.tf32.tf32.f32 "
                 "{%0,%1,%2,%3}, {%4,%5,%6,%7}, {%8,%9}, {%0,%1,%2,%3};"
                 : "+f"(d[0]), "+f"(d[1]), "+f"(d[2]), "+f"(d[3])
                 : "r"(a[0]), "r"(a[1]), "r"(a[2]), "r"(a[3]), "r"(b0), "r"(b1));
}
__device__ __forceinline__ void mma16(float* d, const unsigned* a, unsigned b0, unsigned b1) {
    asm volatile("mma.sync.aligned.m16n8k16.row.col.f32.bf16.bf16.f32 "
                 "{%0,%1,%2,%3}, {%4,%5,%6,%7}, {%8,%9}, {%0,%1,%2,%3};"
                 : "+f"(d[0]), "+f"(d[1]), "+f"(d[2]), "+f"(d[3])
                 : "r"(a[0]), "r"(a[1]), "r"(a[2]), "r"(a[3]), "r"(b0), "r"(b1));
}
__device__ __forceinline__ void ldsm4(unsigned& r0, unsigned& r1, unsigned& r2,
                                      unsigned& r3, unsigned addr) {
    asm volatile("ldmatrix.sync.aligned.m8n8.x4.shared.b16 {%0,%1,%2,%3}, [%4];"
                 : "=r"(r0), "=r"(r1), "=r"(r2), "=r"(r3) : "r"(addr));
}
__device__ __forceinline__ float fast_tanh(float x) {
    float r; asm("tanh.approx.f32 %0, %1;" : "=f"(r) : "f"(x)); return r;
}
__device__ __forceinline__ void cpa16(unsigned dst, const void* src) {
    asm volatile("cp.async.cg.shared.global [%0], [%1], 16;" :: "r"(dst), "l"(src));
}
// expm1(x) for |x| <= ~0.03: quadratic, abs err < 5e-6 (below bf16 pack noise)
__device__ __forceinline__ float expm1_tiny(float x) {
    return x * fmaf(x, 0.5f, 1.0f);
}

// ---------------------------------------------------------------------------
// Prep A: W_vo[h] = W_v[h] @ W_o[h] (fp32 accumulate, bias-rounded store).
// ---------------------------------------------------------------------------
__global__ __launch_bounds__(256) void prep_kernel(const float* __restrict__ Wv,
                                                   const float* __restrict__ Wo) {
    __shared__ float Is[64*64];
    __shared__ float Ws[64*64];
    int h = blockIdx.x, tid = threadIdx.x;

    const float4* a4 = (const float4*)(Wv + h*4096);
    const float4* b4 = (const float4*)(Wo + h*4096);
    for (int i = tid; i < 1024; i += 256) { ((float4*)Is)[i] = a4[i]; ((float4*)Ws)[i] = b4[i]; }
    __syncthreads();

    int tx = tid & 15, ty = tid >> 4;
    int row0 = ty*4, col0 = tx*4;
    float acc[4][4];
    #pragma unroll
    for (int i=0;i<4;i++)
        #pragma unroll
        for (int j=0;j<4;j++) acc[i][j]=0.f;
    #pragma unroll 4
    for (int k4 = 0; k4 < 16; k4++) {
        float a[4][4];
        #pragma unroll
        for (int i=0;i<4;i++) *(float4*)a[i] = *(const float4*)&Is[(row0+i)*64 + k4*4];
        #pragma unroll
        for (int kk=0;kk<4;kk++) {
            float bv[4];
            *(float4*)bv = *(const float4*)&Ws[(k4*4+kk)*64 + col0];
            #pragma unroll
            for (int i=0;i<4;i++)
                #pragma unroll
                for (int j=0;j<4;j++) acc[i][j] += a[i][kk]*bv[j];
        }
    }
    #pragma unroll
    for (int i=0;i<4;i++) {
        float4 v = make_float4(bias_tf32(acc[i][0]), bias_tf32(acc[i][1]),
                               bias_tf32(acc[i][2]), bias_tf32(acc[i][3]));
        *(float4*)(g_wvo + h*4096 + (row0+i)*64 + col0) = v;
    }
}

// ---------------------------------------------------------------------------
// Prep B: Vsum[bh][d] = Sum_t tgt[b,t,h*64+d]. 4-way parallel over t, fixed
// combine order (deterministic).
// ---------------------------------------------------------------------------
__global__ __launch_bounds__(256) void vsum_kernel(const float* __restrict__ tgt) {
    __shared__ float ps[4][64];
    int bh = blockIdx.x;
    int b = bh >> 4, h = bh & 15;
    int d = threadIdx.x & 63;
    int q = threadIdx.x >> 6;
    const float* p = tgt + ((size_t)b*TT + q*256)*EE + h*DD + d;
    float s = 0.f;
    #pragma unroll 8
    for (int t = 0; t < 256; t++) s += p[(size_t)t*EE];
    ps[q][d] = s;
    __syncthreads();
    if (threadIdx.x < 64) {
        int dd = threadIdx.x;
        g_vsum[bh*DD + dd] = ((ps[0][dd] + ps[1][dd]) + (ps[2][dd] + ps[3][dd]));
    }
}

// ---------------------------------------------------------------------------
// Prep C: V transpose to bf16:  g_v2t[bh][d][t] = bf16(tgt[b,t,h*64+d]).
// ---------------------------------------------------------------------------
__global__ __launch_bounds__(256) void vtrans_kernel(const float* __restrict__ tgt) {
    __shared__ float ts[64*68];
    int tt = blockIdx.x, h = blockIdx.y, b = blockIdx.z;
    int bh = b*HH + h;
    int tid = threadIdx.x;

    for (int i = tid; i < 1024; i += 256) {
        int r = i >> 4, c4 = i & 15;
        *(float4*)&ts[r*68 + c4*4] =
            *(const float4*)(tgt + ((size_t)b*TT + tt*64 + r)*EE + h*DD + c4*4);
    }
    __syncthreads();

    for (int j = tid; j < 512; j += 256) {
        int d = j >> 3, ch = j & 7;
        uint4 u;
        u.x = pack_bf16(ts[(ch*8+0)*68 + d], ts[(ch*8+1)*68 + d]);
        u.y = pack_bf16(ts[(ch*8+2)*68 + d], ts[(ch*8+3)*68 + d]);
        u.z = pack_bf16(ts[(ch*8+4)*68 + d], ts[(ch*8+5)*68 + d]);
        u.w = pack_bf16(ts[(ch*8+6)*68 + d], ts[(ch*8+7)*68 + d]);
        ((uint4*)g_v2t)[(size_t)(bh*64 + d)*128 + tt*8 + ch] = u;
    }
}

// ---------------------------------------------------------------------------
// Q projection: q2 = (src @ W_q[h]) / 256, stored bf16 packed per head.
// ---------------------------------------------------------------------------
__global__ __launch_bounds__(256) void proj_kernel(const float* __restrict__ src,
                                                   const float* __restrict__ Wq) {
    __shared__ float Is[64*64];
    __shared__ float Ws[64*64];
    int tt = blockIdx.x, h = blockIdx.y, b = blockIdx.z;
    const float* W = Wq + h * 4096;
    __nv_bfloat16* outp = g_q2 + ((size_t)(b*HH + h)*TT + tt*64)*DD;
    int tid = threadIdx.x;

    for (int i = tid; i < 1024; i += 256) ((float4*)Ws)[i] = ((const float4*)W)[i];
    for (int i = tid; i < 1024; i += 256) {
        int r = i >> 4, c4 = i & 15;
        ((float4*)Is)[i] = *(const float4*)(src + ((size_t)b*TT + tt*64 + r)*EE + h*DD + c4*4);
    }
    __syncthreads();

    int tx = tid & 15, ty = tid >> 4;
    int row0 = ty*4, col0 = tx*4;
    float acc[4][4];
    #pragma unroll
    for (int i=0;i<4;i++)
        #pragma unroll
        for (int j=0;j<4;j++) acc[i][j]=0.f;

    #pragma unroll 4
    for (int k4 = 0; k4 < 16; k4++) {
        float a[4][4];
        #pragma unroll
        for (int i=0;i<4;i++) *(float4*)a[i] = *(const float4*)&Is[(row0+i)*64 + k4*4];
        #pragma unroll
        for (int kk=0;kk<4;kk++) {
            float bv[4];
            *(float4*)bv = *(const float4*)&Ws[(k4*4+kk)*64 + col0];
            #pragma unroll
            for (int i=0;i<4;i++)
                #pragma unroll
                for (int j=0;j<4;j++) acc[i][j] += a[i][kk]*bv[j];
        }
    }
    const float s = 1.0f/256.0f;
    #pragma unroll
    for (int i=0;i<4;i++) {
        uint2 u;
        u.x = pack_bf16(acc[i][0]*s, acc[i][1]*s);
        u.y = pack_bf16(acc[i][2]*s, acc[i][3]*s);
        *(uint2*)(outp + (row0+i)*64 + col0) = u;
    }
}

// ---------------------------------------------------------------------------
// Tensor-core RNN: one block per head h (grid 16), 128 threads (4 warps).
// All 8 batch sequences advance together:  H_next = tanh(H(8x64) @ M^T + c),
// M = W_ih + W_hh held as register-resident bf16 B-fragments (preloaded via
// ldmatrix from a smem tile). Batch b lives in mma row gq (rows 8-15 zero).
// Warp w owns output cols [16w,16w+16): its C values ARE the next step's
// A-fragment chunk w; exchange via a 128-entry bf16x2 smem ring (double buf).
// ---------------------------------------------------------------------------
__global__ __launch_bounds__(128) void rnn_tc_kernel(const float* __restrict__ tgt,
                                                     const float* __restrict__ Wih,
                                                     const float* __restrict__ Whh,
                                                     const float* __restrict__ bih,
                                                     const float* __restrict__ bhh) {
    __shared__ __align__(16) unsigned wih_s[2304];   // Wih tile, rows e, pitch 36 words
    __shared__ __align__(16) unsigned m_s[2304];     // (Wih+Whh) tile
    __shared__ __align__(16) uint2 hx[2][128];       // h exchange: [buf][chunk*32+lane]
    int h = blockIdx.x;
    int tid = threadIdx.x;
    int w = tid >> 5, lane = tid & 31;
    int gq = lane >> 2, tg = lane & 3;

    // ---- build bf16 weight tiles (rows = output col e, words = d-pairs) ----
    for (int idx = tid; idx < 2048; idx += 128) {
        int row = idx >> 5, wd = idx & 31;
        float2 wi = *(const float2*)(Wih + (size_t)(h*64 + row)*64 + 2*wd);
        float2 wh = *(const float2*)(Whh + (size_t)(h*64 + row)*64 + 2*wd);
        wih_s[row*36 + wd] = pack_bf16(wi.x, wi.y);
        m_s[row*36 + wd]   = pack_bf16(wi.x + wh.x, wi.y + wh.y);
    }
    __syncthreads();

    unsigned lmo = (unsigned)(((((lane>>4)*8 + (lane&7))*36) + ((lane>>3)&1)*4) * 4);
    unsigned mbase = (unsigned)__cvta_generic_to_shared(m_s);
    unsigned wbase = (unsigned)__cvta_generic_to_shared(wih_s);

    // preload M fragments for this warp's two n-tiles (cols 16w..16w+15)
    unsigned mb[4][4];
    #pragma unroll
    for (int k = 0; k < 4; k++)
        ldsm4(mb[k][0], mb[k][1], mb[k][2], mb[k][3],
              mbase + (unsigned)(w*2304 + k*32) + lmo);

    // bias for this thread's 4 output cols
    int col0 = w*16 + 2*tg;
    float cb0 = bih[h*DD + col0    ] + bhh[h*DD + col0    ];
    float cb1 = bih[h*DD + col0 + 1] + bhh[h*DD + col0 + 1];
    float cb2 = bih[h*DD + col0 + 8] + bhh[h*DD + col0 + 8];
    float cb3 = bih[h*DD + col0 + 9] + bhh[h*DD + col0 + 9];

    int bh = gq*HH + h;                      // batch = gq (0..7)
    unsigned* nw32 = (unsigned*)g_nw;
    size_t nwb = (size_t)bh*TT*32;           // 32 words (64 bf16) per t
    int wc0 = (col0) >> 1;                   // word of cols col0,col0+1
    int wc2 = (col0 + 8) >> 1;

    // ---- init step: h1 = tanh(W_ih @ k0 + c) ----
    {
        const float* k0p = tgt + (size_t)gq*TT*EE + h*DD;
        unsigned a[4][4];
        #pragma unroll
        for (int k = 0; k < 4; k++) {
            float2 lo = *(const float2*)(k0p + 16*k + 2*tg);
            float2 hi = *(const float2*)(k0p + 16*k + 8 + 2*tg);
            a[k][0] = pack_bf16(lo.x, lo.y);
            a[k][1] = 0u;
            a[k][2] = pack_bf16(hi.x, hi.y);
            a[k][3] = 0u;
        }
        float c0a[4]={0,0,0,0}, c0b[4]={0,0,0,0}, c1a[4]={0,0,0,0}, c1b[4]={0,0,0,0};
        #pragma unroll
        for (int k = 0; k < 4; k++) {
            unsigned b0, b1, b2, b3;
            ldsm4(b0, b1, b2, b3, wbase + (unsigned)(w*2304 + k*32) + lmo);
            if (k < 2) { mma16(c0a, a[k], b0, b1); mma16(c1a, a[k], b2, b3); }
            else       { mma16(c0b, a[k], b0, b1); mma16(c1b, a[k], b2, b3); }
        }
        float v0 = fast_tanh(c0a[0]+c0b[0] + cb0);
        float v1 = fast_tanh(c0a[1]+c0b[1] + cb1);
        float v2 = fast_tanh(c1a[0]+c1b[0] + cb2);
        float v3 = fast_tanh(c1a[1]+c1b[1] + cb3);
        unsigned p0 = pack_bf16(v0, v1), p1 = pack_bf16(v2, v3);
        hx[0][w*32 + lane] = make_uint2(p0, p1);
        nw32[nwb + wc0] = p0;
        nw32[nwb + wc2] = p1;
    }
    __syncthreads();

    // ---- recurrence ----
    int cur = 0;
    for (int t = 1; t < TT; t++) {
        uint2 ha0 = hx[cur][lane], ha1 = hx[cur][32 + lane];
        uint2 ha2 = hx[cur][64 + lane], ha3 = hx[cur][96 + lane];
        unsigned a0[4] = { ha0.x, 0u, ha0.y, 0u };
        unsigned a1[4] = { ha1.x, 0u, ha1.y, 0u };
        unsigned a2[4] = { ha2.x, 0u, ha2.y, 0u };
        unsigned a3[4] = { ha3.x, 0u, ha3.y, 0u };
        float c0a[4]={0,0,0,0}, c0b[4]={0,0,0,0}, c1a[4]={0,0,0,0}, c1b[4]={0,0,0,0};
        mma16(c0a, a0, mb[0][0], mb[0][1]);  mma16(c1a, a0, mb[0][2], mb[0][3]);
        mma16(c0a, a1, mb[1][0], mb[1][1]);  mma16(c1a, a1, mb[1][2], mb[1][3]);
        mma16(c0b, a2, mb[2][0], mb[2][1]);  mma16(c1b, a2, mb[2][2], mb[2][3]);
        mma16(c0b, a3, mb[3][0], mb[3][1]);  mma16(c1b, a3, mb[3][2], mb[3][3]);
        float v0 = fast_tanh(c0a[0]+c0b[0] + cb0);
        float v1 = fast_tanh(c0a[1]+c0b[1] + cb1);
        float v2 = fast_tanh(c1a[0]+c1b[0] + cb2);
        float v3 = fast_tanh(c1a[1]+c1b[1] + cb3);
        unsigned p0 = pack_bf16(v0, v1), p1 = pack_bf16(v2, v3);
        hx[cur^1][w*32 + lane] = make_uint2(p0, p1);
        size_t nwt = nwb + (size_t)t*32;
        nw32[nwt + wc0] = p0;
        nw32[nwt + wc2] = p1;
        cur ^= 1;
        __syncthreads();
    }
}

// ---------------------------------------------------------------------------
// Flash attention (single pass, round-13 proven): mean-subtracted
//   O = Vsum + E @ V,  E = expm1(scores),  l = 1024 + sum(E)
// bf16 mma; B-frags via ldmatrix.x4; 3-stage cp.async, one barrier/ktile.
// ---------------------------------------------------------------------------
#define STG3_W 4608

__global__ __launch_bounds__(256, 2) void attn_kernel(float* __restrict__ out) {
    extern __shared__ float sm[];   // 13824 words
    unsigned* smw = (unsigned*)sm;
    int qt = blockIdx.x, h = blockIdx.y, b = blockIdx.z;
    int bh = b*HH + h;
    int tid = threadIdx.x;
    int w = tid >> 5, lane = tid & 31;
    int gq = lane >> 2;
    int tg = lane & 3;
    int r0 = w * 16;
    unsigned sb = (unsigned)__cvta_generic_to_shared(sm);
    unsigned lmo = (unsigned)(((((lane>>4)*8 + (lane&7))*36) + ((lane>>3)&1)*4) * 4);

    // ---- stage Q tile [128][64] bf16 -> smem word pitch 36; extract frags ----
    {
        const uint4* qsrc = (const uint4*)(g_q2 + ((size_t)bh*TT + qt*128)*DD);
        #pragma unroll
        for (int j = 0; j < 4; j++) {
            int idx = tid + j*256;
            int r = idx >> 3, c = idx & 7;
            cpa16(sb + ((unsigned)(r*36 + c*4))*4u, qsrc + idx);
        }
        asm volatile("cp.async.commit_group;");
        asm volatile("cp.async.wait_group 0;");
    }
    __syncthreads();
    unsigned qa[4][4];
    #pragma unroll
    for (int k = 0; k < 4; k++) {
        qa[k][0] = smw[(r0+gq  )*36 + k*8 + tg  ];
        qa[k][1] = smw[(r0+gq+8)*36 + k*8 + tg  ];
        qa[k][2] = smw[(r0+gq  )*36 + k*8 + tg+4];
        qa[k][3] = smw[(r0+gq+8)*36 + k*8 + tg+4];
    }
    __syncthreads();   // frags in regs before staging overwrites

    const uint4* kg = (const uint4*)(g_nw + (size_t)bh*TT*DD);
    const uint4* vt = (const uint4*)g_v2t + (size_t)(bh*64)*128;

    // ---- prologue: stage tiles 0 and 1 into buffers 0, 1 ----
    #pragma unroll
    for (int pt = 0; pt < 2; pt++) {
        unsigned bb = (unsigned)(pt * STG3_W) * 4u;
        const uint4* kp = kg + (size_t)pt*512;
        const uint4* vp = vt + pt*8;
        #pragma unroll
        for (int j = 0; j < 2; j++) {
            int idx = tid + j*256;
            int r = idx >> 3, c = idx & 7;
            cpa16(sb + bb + ((unsigned)(r*36 + c*4))*4u, kp + idx);
        }
        #pragma unroll
        for (int j = 0; j < 2; j++) {
            int idx = tid + j*256;
            int d = idx >> 3, c = idx & 7;
            cpa16(sb + bb + ((unsigned)(2304 + d*36 + c*4))*4u, vp + (size_t)d*128 + c);
        }
        asm volatile("cp.async.commit_group;");
    }

    float l0 = 1024.f, l1 = 1024.f;
    float o[8][4];
    #pragma unroll
    for (int n=0;n<8;n++) { o[n][0]=0.f;o[n][1]=0.f;o[n][2]=0.f;o[n][3]=0.f; }

    for (int kt = 0; kt < 16; kt++) {
        if (kt < 15) asm volatile("cp.async.wait_group 1;");
        else         asm volatile("cp.async.wait_group 0;");
        __syncthreads();   // tile kt ready; all warps done reading tile kt-1

        if (kt < 14) {
            int sidx = (kt+2) % 3;
            unsigned bb = (unsigned)(sidx * STG3_W) * 4u;
            const uint4* kp = kg + (size_t)(kt+2)*512;
            const uint4* vp = vt + (kt+2)*8;
            #pragma unroll
            for (int j = 0; j < 2; j++) {
                int idx = tid + j*256;
                int r = idx >> 3, c = idx & 7;
                cpa16(sb + bb + ((unsigned)(r*36 + c*4))*4u, kp + idx);
            }
            #pragma unroll
            for (int j = 0; j < 2; j++) {
                int idx = tid + j*256;
                int d = idx >> 3, c = idx & 7;
                cpa16(sb + bb + ((unsigned)(2304 + d*36 + c*4))*4u, vp + (size_t)d*128 + c);
            }
            asm volatile("cp.async.commit_group;");
        }

        unsigned kaddr = sb + (unsigned)((kt % 3) * STG3_W) * 4u + lmo;
        unsigned vaddr = kaddr + 2304u*4u;

        // ---- S = Q @ K^T (bf16, Q pre-scaled by 1/256); B via ldmatrix.x4 ----
        float s[8][4];
        #pragma unroll
        for (int n=0;n<8;n++) { s[n][0]=0.f;s[n][1]=0.f;s[n][2]=0.f;s[n][3]=0.f; }
        #pragma unroll
        for (int np = 0; np < 4; np++) {
            #pragma unroll
            for (int k = 0; k < 4; k++) {
                unsigned b0, b1, b2, b3;
                ldsm4(b0, b1, b2, b3, kaddr + (unsigned)np*2304u + (unsigned)k*32u);
                mma16(s[2*np  ], qa[k], b0, b1);
                mma16(s[2*np+1], qa[k], b2, b3);
            }
        }

        // ---- E = expm1(s); l += sum(E) ----
        float ls0 = 0.f, ls1 = 0.f;
        #pragma unroll
        for (int n = 0; n < 8; n++) {
            s[n][0] = expm1_tiny(s[n][0]); s[n][1] = expm1_tiny(s[n][1]);
            s[n][2] = expm1_tiny(s[n][2]); s[n][3] = expm1_tiny(s[n][3]);
            ls0 += s[n][0] + s[n][1];
            ls1 += s[n][2] + s[n][3];
        }
        ls0 += __shfl_xor_sync(0xffffffffu, ls0, 1);
        ls0 += __shfl_xor_sync(0xffffffffu, ls0, 2);
        ls1 += __shfl_xor_sync(0xffffffffu, ls1, 1);
        ls1 += __shfl_xor_sync(0xffffffffu, ls1, 2);
        l0 += ls0;
        l1 += ls1;

        // ---- O += E @ V (A-frags straight from C-layout; B via ldmatrix.x4) ----
        unsigned ap[4][4];
        #pragma unroll
        for (int m = 0; m < 4; m++) {
            ap[m][0] = pack_bf16(s[2*m  ][0], s[2*m  ][1]);
            ap[m][1] = pack_bf16(s[2*m  ][2], s[2*m  ][3]);
            ap[m][2] = pack_bf16(s[2*m+1][0], s[2*m+1][1]);
            ap[m][3] = pack_bf16(s[2*m+1][2], s[2*m+1][3]);
        }
        #pragma unroll
        for (int np = 0; np < 4; np++) {
            #pragma unroll
            for (int m = 0; m < 4; m++) {
                unsigned b0, b1, b2, b3;
                ldsm4(b0, b1, b2, b3, vaddr + (unsigned)np*2304u + (unsigned)m*32u);
                mma16(o[2*np  ], ap[m], b0, b1);
                mma16(o[2*np+1], ap[m], b2, b3);
            }
        }
    }
    __syncthreads();   // all tile-15 reads done before epilogue reuses smem

    // ---- fused epilogue: out_rows = ((Vsum + O)/l) @ W_vo[h] ----
    float inv0 = 1.0f/l0, inv1 = 1.0f/l1;
    float2 vs[8];
    #pragma unroll
    for (int n = 0; n < 8; n++)
        vs[n] = *(const float2*)&g_vsum[bh*64 + n*8 + 2*tg];

    float* Os = sm;              // pitch 72, words [0, 9216)
    float* WvT = sm + 9216;      // words [9216, 13824)
    #pragma unroll
    for (int n = 0; n < 8; n++) {
        Os[(r0+gq  )*72 + n*8 + 2*tg  ] = (o[n][0]+vs[n].x)*inv0;
        Os[(r0+gq  )*72 + n*8 + 2*tg+1] = (o[n][1]+vs[n].y)*inv0;
        Os[(r0+gq+8)*72 + n*8 + 2*tg  ] = (o[n][2]+vs[n].x)*inv1;
        Os[(r0+gq+8)*72 + n*8 + 2*tg+1] = (o[n][3]+vs[n].y)*inv1;
    }
    const float* wv = g_wvo + h*4096;   // already bias-rounded
    for (int i = tid; i < 1024; i += 256) {
        int k = i >> 4, n4 = (i & 15) * 4;
        float4 v = *(const float4*)(wv + k*64 + n4);
        WvT[(n4  )*72 + k] = v.x;
        WvT[(n4+1)*72 + k] = v.y;
        WvT[(n4+2)*72 + k] = v.z;
        WvT[(n4+3)*72 + k] = v.w;
    }
    __syncthreads();

    float r2[8][4];
    #pragma unroll
    for (int n=0;n<8;n++) { r2[n][0]=0.f;r2[n][1]=0.f;r2[n][2]=0.f;r2[n][3]=0.f; }
    #pragma unroll
    for (int k = 0; k < 8; k++) {
        unsigned a[4];
        a[0] = cvt_tf32(Os[(r0+gq  )*72 + k*8 + tg  ]);
        a[1] = cvt_tf32(Os[(r0+gq+8)*72 + k*8 + tg  ]);
        a[2] = cvt_tf32(Os[(r0+gq  )*72 + k*8 + tg+4]);
        a[3] = cvt_tf32(Os[(r0+gq+8)*72 + k*8 + tg+4]);
        #pragma unroll
        for (int n = 0; n < 8; n++) {
            unsigned b0 = __float_as_uint(WvT[(n*8+gq)*72 + k*8 + tg  ]);
            unsigned b1 = __float_as_uint(WvT[(n*8+gq)*72 + k*8 + tg+4]);
            mma8(r2[n], a, b0, b1);
        }
    }
    float* op = out + ((size_t)b*TT + qt*128)*EE + h*DD;
    #pragma unroll
    for (int n = 0; n < 8; n++) {
        *(float2*)(op + (size_t)(r0+gq  )*EE + n*8 + 2*tg) = make_float2(r2[n][0], r2[n][1]);
        *(float2*)(op + (size_t)(r0+gq+8)*EE + n*8 + 2*tg) = make_float2(r2[n][2], r2[n][3]);
    }
}

// ---------------------------------------------------------------------------
extern "C" void kernel_launch(void* const* d_in, const int* in_sizes, int n_in,
                              void* d_out, int out_size) {
    const float* src = (const float*)d_in[0];
    const float* tgt = (const float*)d_in[1];
    const float* Wq  = (const float*)d_in[2];
    const float* Wv  = (const float*)d_in[3];
    const float* Wo  = (const float*)d_in[4];
    const float* Wih = (const float*)d_in[5];
    const float* Whh = (const float*)d_in[6];
    const float* bih = (const float*)d_in[7];
    const float* bhh = (const float*)d_in[8];
    float* out = (float*)d_out;

    // One-time infra (host-side only; no device memory).
    static cudaStream_t s_rnn = nullptr, s_aux = nullptr;
    static cudaEvent_t ev_fork = nullptr, ev_rnn = nullptr, ev_aux = nullptr;
    if (s_rnn == nullptr) {
        cudaStreamCreateWithFlags(&s_rnn, cudaStreamNonBlocking);
        cudaStreamCreateWithFlags(&s_aux, cudaStreamNonBlocking);
        cudaEventCreateWithFlags(&ev_fork, cudaEventDisableTiming);
        cudaEventCreateWithFlags(&ev_rnn, cudaEventDisableTiming);
        cudaEventCreateWithFlags(&ev_aux, cudaEventDisableTiming);
        cudaFuncSetAttribute(attn_kernel, cudaFuncAttributeMaxDynamicSharedMemorySize,
                             3 * STG3_W * (int)sizeof(float));
    }

    cudaEventRecord(ev_fork, 0);

    // stream R: tensor-core RNN (16 blocks — leaves the chip to the preps).
    cudaStreamWaitEvent(s_rnn, ev_fork, 0);
    rnn_tc_kernel<<<16, 128, 0, s_rnn>>>(tgt, Wih, Whh, bih, bhh);
    cudaEventRecord(ev_rnn, s_rnn);

    // stream AUX: epilogue inputs.
    cudaStreamWaitEvent(s_aux, ev_fork, 0);
    prep_kernel<<<16, 256, 0, s_aux>>>(Wv, Wo);
    vsum_kernel<<<128, 256, 0, s_aux>>>(tgt);
    cudaEventRecord(ev_aux, s_aux);

    // stream 0: attention inputs, then attention.
    vtrans_kernel<<<dim3(16,16,8), 256>>>(tgt);
    proj_kernel<<<dim3(16,16,8), 256>>>(src, Wq);

    cudaStreamWaitEvent(0, ev_rnn, 0);
    cudaStreamWaitEvent(0, ev_aux, 0);
    attn_kernel<<<dim3(8, 16, 8), 256, 3 * STG3_W * sizeof(float)>>>(out);
}